// round 16
// baseline (speedup 1.0000x reference)
#include <cuda_runtime.h>
#include <cuda_bf16.h>
#include <math.h>
#include <cstdint>

// Problem constants
//   outputs/targets:           [4, 3, 256, 256]  -> 786432 floats
//   output/target features:    [4, 256, 64, 64]  -> B=4, C=256, N=4096
#define Bn   4
#define Cn   256
#define Nn   4096
#define IMG_ELEMS  786432
#define FEAT_ELEMS 4194304
#define EPS1 1e-8f
#define EPS2 1e-5f

// ---------------- device scratch (allocation-free: static globals) ----------
static __device__ __nv_bfloat16 g_Xh[Bn * Nn * Cn];   // centered out-feats bf16
static __device__ __nv_bfloat16 g_Yh[Bn * Nn * Cn];   // centered tgt-feats bf16
static __device__ int8_t g_Xq[Bn * Nn * Cn];          // row-quantized X (int8)
static __device__ int8_t g_Yq[Bn * Nn * Cn];          // row-quantized Y (int8)
static __device__ float  g_mean[2][Bn * Cn];          // per-(b,c) means
static __device__ float  g_xn[Bn * Nn];               // |qx| int-vector norms
static __device__ float  g_yn[Bn * Nn];               // |qy| int-vector norms
static __device__ __nv_bfloat16 g_cosh[(size_t)Bn * Nn * Nn]; // 128 MB cosine
static __device__ float  g_pS[Bn * Nn];               // per-row scale s = 1/(dmin+eps2)
static __device__ float  g_pA[Bn * Nn];               // per-row affine (1-s)-log(rowsum)
static __device__ float  g_cmax[8 * Bn * Nn];         // partial col maxima (8 x-chunks)
static __device__ double g_msep[2][512];              // MSE block partials

// ---------------- helpers ----------------------------------------------------
__device__ __forceinline__ uint32_t smem_u32(const void* p) {
    uint32_t a;
    asm("{ .reg .u64 t; cvta.to.shared.u64 t, %1; cvt.u32.u64 %0, t; }"
        : "=r"(a) : "l"(p));
    return a;
}
#define CP_ASYNC16(dst, src) \
    asm volatile("cp.async.cg.shared.global [%0], [%1], 16;" \
                 :: "r"(dst), "l"(src) : "memory")
#define CP_COMMIT() asm volatile("cp.async.commit_group;" ::: "memory")
#define CP_WAIT(n)  asm volatile("cp.async.wait_group %0;" :: "n"(n) : "memory")

__device__ __forceinline__ float2 bf2f(uint32_t u) {
    __nv_bfloat162 h;
    *reinterpret_cast<uint32_t*>(&h) = u;
    return __bfloat1622float2(h);
}

// ldmatrix x4: four 8x8 b16 tiles, addresses supplied per-lane
__device__ __forceinline__ void ldmx4(uint32_t* r, uint32_t addr) {
    asm volatile(
        "ldmatrix.sync.aligned.m8n8.x4.shared.b16 {%0,%1,%2,%3}, [%4];"
        : "=r"(r[0]), "=r"(r[1]), "=r"(r[2]), "=r"(r[3]) : "r"(addr));
}

// warp-level int8 MMA: D(16x8,s32) += A(16x32,s8) * B(32x8,s8)
__device__ __forceinline__ void mma_s8(int* d, const uint32_t* a,
                                       uint32_t b0, uint32_t b1) {
    asm volatile(
        "mma.sync.aligned.m16n8k32.row.col.s32.s8.s8.s32 "
        "{%0,%1,%2,%3}, {%4,%5,%6,%7}, {%8,%9}, {%0,%1,%2,%3};"
        : "+r"(d[0]), "+r"(d[1]), "+r"(d[2]), "+r"(d[3])
        : "r"(a[0]), "r"(a[1]), "r"(a[2]), "r"(a[3]), "r"(b0), "r"(b1));
}

// ---------------- 1. MSE partials (deterministic two-stage) ------------------
__global__ void __launch_bounds__(256) mse_kernel(const float* __restrict__ o,
                                                  const float* __restrict__ t,
                                                  const float* __restrict__ of,
                                                  const float* __restrict__ tf) {
    const int which = blockIdx.y;
    const float* a = which ? of : o;
    const float* c = which ? tf : t;
    const int n = which ? FEAT_ELEMS : IMG_ELEMS;
    double s = 0.0;
    for (int i = blockIdx.x * 256 + threadIdx.x; i < n; i += 512 * 256) {
        float d = a[i] - c[i];
        s += (double)d * (double)d;
    }
    __shared__ double sh[256];
    sh[threadIdx.x] = s;
    __syncthreads();
    for (int st = 128; st > 0; st >>= 1) {
        if (threadIdx.x < st) sh[threadIdx.x] += sh[threadIdx.x + st];
        __syncthreads();
    }
    if (threadIdx.x == 0) g_msep[which][blockIdx.x] = sh[0];
}

// ---------------- 2. per-(b,c) means over N positions ------------------------
__global__ void __launch_bounds__(256) mean_kernel(const float* __restrict__ of,
                                                   const float* __restrict__ tf) {
    const float* src = blockIdx.y ? tf : of;
    const int bc = blockIdx.x;
    const float* p = src + (size_t)bc * Nn;
    float s = 0.f;
    for (int i = threadIdx.x; i < Nn; i += 256) s += p[i];
    __shared__ float sh[256];
    sh[threadIdx.x] = s;
    __syncthreads();
    for (int st = 128; st > 0; st >>= 1) {
        if (threadIdx.x < st) sh[threadIdx.x] += sh[threadIdx.x + st];
        __syncthreads();
    }
    if (threadIdx.x == 0) g_mean[blockIdx.y][bc] = sh[0] * (1.f / Nn);
}

// ---------------- 3. transpose [C][N] -> [N][C], center, cast bf16 -----------
__global__ void __launch_bounds__(256) transpose_kernel(const float* __restrict__ of,
                                                        const float* __restrict__ tf) {
    const int tz = blockIdx.z;
    const int tensor = tz >> 2;
    const int b = tz & 3;
    const float* src = (tensor ? tf : of) + (size_t)b * Cn * Nn;
    __nv_bfloat16* dst = (tensor ? g_Yh : g_Xh) + (size_t)b * Nn * Cn;
    const float* mean = g_mean[tensor] + b * Cn;
    __shared__ float tile[32][33];
    const int tx = threadIdx.x, ty = threadIdx.y;  // 32 x 8
    const int n0 = blockIdx.x * 32, c0 = blockIdx.y * 32;
#pragma unroll
    for (int j = 0; j < 4; j++) {
        int c = c0 + ty + j * 8;
        tile[ty + j * 8][tx] = src[(size_t)c * Nn + n0 + tx] - mean[c];
    }
    __syncthreads();
#pragma unroll
    for (int j = 0; j < 4; j++) {
        int n = n0 + ty + j * 8;
        dst[(size_t)n * Cn + c0 + tx] = __float2bfloat16(tile[tx][ty + j * 8]);
    }
}

// ---------------- 4. per-row quantize to int8 + integer norm ------------------
// cosine is row-scale invariant: q = round(127*x/max|row|), norm = sqrt(sum q^2)
__global__ void __launch_bounds__(256) quant_kernel() {
    const int tensor = blockIdx.y;
    const __nv_bfloat16* X = tensor ? g_Yh : g_Xh;
    int8_t* Q = tensor ? g_Yq : g_Xq;
    float* out = tensor ? g_yn : g_xn;
    const int warp = threadIdx.x >> 5, lane = threadIdx.x & 31;
    const int r = blockIdx.x * 8 + warp;
    const uint4* p = (const uint4*)(X + (size_t)r * Cn);
    uint4 q = p[lane];  // 8 bf16
    const uint32_t* w = (const uint32_t*)&q;
    float v[8];
#pragma unroll
    for (int i = 0; i < 4; i++) {
        float2 f = bf2f(w[i]);
        v[2 * i] = f.x; v[2 * i + 1] = f.y;
    }
    float m = 0.f;
#pragma unroll
    for (int i = 0; i < 8; i++) m = fmaxf(m, fabsf(v[i]));
    for (int o = 16; o; o >>= 1) m = fmaxf(m, __shfl_xor_sync(0xffffffffu, m, o));
    const float inv = (m > 0.f) ? (127.f / m) : 0.f;
    int qi[8], ssq = 0;
#pragma unroll
    for (int i = 0; i < 8; i++) {
        qi[i] = __float2int_rn(v[i] * inv);
        ssq += qi[i] * qi[i];
    }
    uint2 pk;
    pk.x = (uint32_t)(qi[0] & 255) | ((uint32_t)(qi[1] & 255) << 8) |
           ((uint32_t)(qi[2] & 255) << 16) | ((uint32_t)(qi[3] & 255) << 24);
    pk.y = (uint32_t)(qi[4] & 255) | ((uint32_t)(qi[5] & 255) << 8) |
           ((uint32_t)(qi[6] & 255) << 16) | ((uint32_t)(qi[7] & 255) << 24);
    *(uint2*)(Q + (size_t)r * Cn + lane * 8) = pk;
    for (int o = 16; o; o >>= 1) ssq += __shfl_xor_sync(0xffffffffu, ssq, o);
    if (lane == 0) out[r] = sqrtf((float)ssq);
}

// ---------------- 5. int8 mma.sync GEMM -> bf16 cosine matrix ----------------
// BM=128, BN=128, BK=64 (int8), 256 threads (8 warps, 2x4 grid, warp 64x32).
// 3-stage cp.async pipeline; ldmatrix.x4 fragments; exact int32 accumulation.
// Smem rows = 64 B (one 64-int8 K-chunk); XOR swizzle on 16B groups.
__global__ void __launch_bounds__(256) gemm_mma_kernel() {
    __shared__ __align__(16) uint32_t smem[12288];  // 3 stages x (A 8KB | B 8KB)

    const int b = blockIdx.z;
    const int rowBase = blockIdx.y * 128, colBase = blockIdx.x * 128;
    const int8_t* __restrict__ Xb = g_Xq + (size_t)b * (Nn * Cn);
    const int8_t* __restrict__ Yb = g_Yq + (size_t)b * (Nn * Cn);
    const int tid = threadIdx.x;
    const int wid = tid >> 5, lane = tid & 31;
    const int wm = wid & 1, wn = wid >> 1;   // 2 along M, 4 along N
    const int g = lane >> 2, c = lane & 3;

    // cp.async staging: 128 rows x 64 B per operand per chunk; 2 xfers/thread/op
    const int row0 = tid >> 2, tq = tid & 3;
    const int8_t* Agp = Xb + (size_t)(rowBase + row0) * Cn + tq * 16;
    const int8_t* Bgp = Yb + (size_t)(colBase + row0) * Cn + tq * 16;
    const uint32_t sbase = smem_u32(smem);
    const uint32_t soff = (uint32_t)(row0 * 64 + (tq ^ ((row0 >> 1) & 3)) * 16);

#define ISSUE(ch, st) do {                                                    \
        const uint32_t dA = sbase + (uint32_t)(st) * 16384u + soff;           \
        const uint32_t dB = dA + 8192u;                                       \
        CP_ASYNC16(dA,        Agp + (ch) * 64);                               \
        CP_ASYNC16(dA + 4096, Agp + 64 * Cn + (ch) * 64);                     \
        CP_ASYNC16(dB,        Bgp + (ch) * 64);                               \
        CP_ASYNC16(dB + 4096, Bgp + 64 * Cn + (ch) * 64);                     \
        CP_COMMIT();                                                          \
    } while (0)

    int d[4][4][4];
#pragma unroll
    for (int mt = 0; mt < 4; mt++)
#pragma unroll
        for (int nt = 0; nt < 4; nt++)
#pragma unroll
            for (int k = 0; k < 4; k++) d[mt][nt][k] = 0;

    // ldmatrix per-lane address geometry (same byte shape as bf16 k16 case)
    const int arow = wm * 64 + (lane & 15);        // + mt*16
    const int ahi = lane >> 4;                     // 16B-group half select
    const uint32_t asw = (uint32_t)((arow >> 1) & 3);
    const uint32_t aoff = (uint32_t)(arow * 64);
    const int brow = wn * 32 + lane;               // covers 4 n-tiles of 8 rows
    const uint32_t bsw = (uint32_t)((brow >> 1) & 3);
    const uint32_t boff = 8192u + (uint32_t)(brow * 64);

    ISSUE(0, 0);
    ISSUE(1, 1);
    int stage = 0;
    for (int ch = 0; ch < 4; ch++) {
        if (ch < 2) {
            int nst = stage + 2; if (nst >= 3) nst -= 3;
            ISSUE(ch + 2, nst);
            CP_WAIT(2);
        } else if (ch == 2) {
            CP_WAIT(1);
        } else {
            CP_WAIT(0);
        }
        __syncthreads();

        const uint32_t sb = sbase + (uint32_t)stage * 16384u;
        const uint32_t abase = sb + aoff;
        const uint32_t bbase = sb + boff;
#pragma unroll
        for (int kk = 0; kk < 2; kk++) {
            uint32_t af[4][4], b0[4], b1[4];
            const uint32_t akg = (uint32_t)(kk * 2 + ahi);
#pragma unroll
            for (int mt = 0; mt < 4; mt++)
                ldmx4(af[mt], abase + (uint32_t)(mt * 1024) + ((akg ^ asw) << 4));
            ldmx4(b0, bbase + (((uint32_t)(kk * 2) ^ bsw) << 4));
            ldmx4(b1, bbase + (((uint32_t)(kk * 2 + 1) ^ bsw) << 4));
#pragma unroll
            for (int mt = 0; mt < 4; mt++)
#pragma unroll
                for (int nt = 0; nt < 4; nt++)
                    mma_s8(d[mt][nt], af[mt], b0[nt], b1[nt]);
        }
        __syncthreads();
        if (++stage == 3) stage = 0;
    }
#undef ISSUE

    // ---- epilogue: cosine normalization + bf16 store ----
    // cos = (int dot) / (|qx| * |qy| + eps) -- exact cosine of quantized rows
    const float* xn = g_xn + (b << 12);
    const float* yn = g_yn + (b << 12);
    float xv[4][2], yv[4][2];
#pragma unroll
    for (int mt = 0; mt < 4; mt++) {
        const int r = rowBase + wm * 64 + mt * 16 + g;
        xv[mt][0] = xn[r];
        xv[mt][1] = xn[r + 8];
    }
#pragma unroll
    for (int nt = 0; nt < 4; nt++) {
        const int cc = colBase + wn * 32 + nt * 8 + 2 * c;
        yv[nt][0] = yn[cc];
        yv[nt][1] = yn[cc + 1];
    }
    __nv_bfloat16* Cb = g_cosh + ((size_t)b << 24);
#pragma unroll
    for (int mt = 0; mt < 4; mt++) {
        const int r = rowBase + wm * 64 + mt * 16 + g;
#pragma unroll
        for (int nt = 0; nt < 4; nt++) {
            const int cc = colBase + wn * 32 + nt * 8 + 2 * c;
            __nv_bfloat162 o0 = __floats2bfloat162_rn(
                (float)d[mt][nt][0] / (xv[mt][0] * yv[nt][0] + EPS1),
                (float)d[mt][nt][1] / (xv[mt][0] * yv[nt][1] + EPS1));
            __nv_bfloat162 o1 = __floats2bfloat162_rn(
                (float)d[mt][nt][2] / (xv[mt][1] * yv[nt][0] + EPS1),
                (float)d[mt][nt][3] / (xv[mt][1] * yv[nt][1] + EPS1));
            *(__nv_bfloat162*)(Cb + (size_t)r * Nn + cc) = o0;
            *(__nv_bfloat162*)(Cb + (size_t)(r + 8) * Nn + cc) = o1;
        }
    }
}

// ---------------- 6. row pass: warp-per-row, shfl-only reductions -------------
// d = 1-cos; s = 1/(dmin+eps2); w_y = exp((1-s) + cos_y*s)
__global__ void __launch_bounds__(256) rowpass_kernel() {
    const int warp = threadIdx.x >> 5, lane = threadIdx.x & 31;
    const int r = blockIdx.x * 8 + warp;  // b*Nn + x
    const uint4* row = (const uint4*)(g_cosh + (size_t)r * Nn);
    uint4 q[16];
#pragma unroll
    for (int j = 0; j < 16; j++) q[j] = row[lane + 32 * j];

    float m = -1e30f;
#pragma unroll
    for (int j = 0; j < 16; j++) {
        const uint32_t* w = (const uint32_t*)&q[j];
#pragma unroll
        for (int i = 0; i < 4; i++) {
            float2 f = bf2f(w[i]);
            m = fmaxf(m, fmaxf(f.x, f.y));
        }
    }
    for (int o = 16; o; o >>= 1) m = fmaxf(m, __shfl_xor_sync(0xffffffffu, m, o));

    const float s = 1.f / (1.f - m + EPS2);
    const float a = 1.f - s;
    float sum = 0.f;
#pragma unroll
    for (int j = 0; j < 16; j++) {
        const uint32_t* w = (const uint32_t*)&q[j];
#pragma unroll
        for (int i = 0; i < 4; i++) {
            float2 f = bf2f(w[i]);
            sum += __expf(fmaf(f.x, s, a)) + __expf(fmaf(f.y, s, a));
        }
    }
    for (int o = 16; o; o >>= 1) sum += __shfl_xor_sync(0xffffffffu, sum, o);

    if (lane == 0) {
        g_pS[r] = s;
        g_pA[r] = a - logf(sum);
    }
}

// ---------------- 7. column pass: partial max over x (log-domain) ------------
// log c[x][y] = cos*s_x + A_x -> max over 512-row x-chunk, 2 y per thread
__global__ void __launch_bounds__(256) colpass_kernel() {
    const int tid = threadIdx.x;
    const int ypair = blockIdx.x * 256 + tid;  // 0..2047 (y = 2*ypair)
    const int chunk = blockIdx.y;              // 0..7
    const int b = blockIdx.z;                  // 0..3
    __shared__ float ss[512], sa[512];
    const int r0 = (b << 12) + (chunk << 9);
    for (int i = tid; i < 512; i += 256) {
        ss[i] = g_pS[r0 + i];
        sa[i] = g_pA[r0 + i];
    }
    __syncthreads();
    const uint32_t* base =
        (const uint32_t*)(g_cosh + ((size_t)b << 24) + ((size_t)chunk << 21)) + ypair;
    float m0 = -1e30f, m1 = -1e30f;
#pragma unroll 8
    for (int x = 0; x < 512; x++) {
        float2 f = bf2f(base[(size_t)x << 11]);
        m0 = fmaxf(m0, fmaf(f.x, ss[x], sa[x]));
        m1 = fmaxf(m1, fmaf(f.y, ss[x], sa[x]));
    }
    const int y = ypair * 2;
    g_cmax[(chunk << 14) + (b << 12) + y] = m0;
    g_cmax[(chunk << 14) + (b << 12) + y + 1] = m1;
}

// ---------------- 8. final: CS, MSEs, loss -----------------------------------
__global__ void __launch_bounds__(256) final_kernel(float* __restrict__ out) {
    const int tid = threadIdx.x;
    double cs = 0.0;
    for (int i = tid; i < Bn * Nn; i += 256) {
        float m = -1e30f;
#pragma unroll
        for (int ch = 0; ch < 8; ch++) m = fmaxf(m, g_cmax[(ch << 14) + i]);
        cs += exp((double)m);
    }
    double m1 = 0.0, m2 = 0.0;
    for (int i = tid; i < 512; i += 256) {
        m1 += g_msep[0][i];
        m2 += g_msep[1][i];
    }
    __shared__ double sh[3][256];
    sh[0][tid] = cs; sh[1][tid] = m1; sh[2][tid] = m2;
    __syncthreads();
    for (int st = 128; st > 0; st >>= 1) {
        if (tid < st) {
            sh[0][tid] += sh[0][tid + st];
            sh[1][tid] += sh[1][tid + st];
            sh[2][tid] += sh[2][tid + st];
        }
        __syncthreads();
    }
    if (tid == 0) {
        double CS = sh[0][0] / (double)(Bn * Nn);
        double mse1 = sh[1][0] / (double)IMG_ELEMS;
        double perc = sh[2][0] / (double)FEAT_ELEMS;
        out[0] = (float)(mse1 - log(CS) + 0.02 * perc);
    }
}

// ---------------- launch ------------------------------------------------------
extern "C" void kernel_launch(void* const* d_in, const int* in_sizes, int n_in,
                              void* d_out, int out_size) {
    const float* outputs = (const float*)d_in[0];
    const float* targets = (const float*)d_in[1];
    const float* of = (const float*)d_in[2];
    const float* tf = (const float*)d_in[3];
    float* out = (float*)d_out;

    mse_kernel<<<dim3(512, 2), 256>>>(outputs, targets, of, tf);
    mean_kernel<<<dim3(Bn * Cn, 2), 256>>>(of, tf);
    transpose_kernel<<<dim3(Nn / 32, Cn / 32, 2 * Bn), dim3(32, 8)>>>(of, tf);
    quant_kernel<<<dim3(Bn * Nn / 8, 2), 256>>>();
    gemm_mma_kernel<<<dim3(Nn / 128, Nn / 128, Bn), 256>>>();
    rowpass_kernel<<<Bn * Nn / 8, 256>>>();
    colpass_kernel<<<dim3(Nn / 512, 8, Bn), 256>>>();
    final_kernel<<<1, 256>>>(out);
}

// round 17
// speedup vs baseline: 1.4222x; 1.4222x over previous
#include <cuda_runtime.h>
#include <cuda_bf16.h>
#include <math.h>
#include <cstdint>

// Problem constants
//   outputs/targets:           [4, 3, 256, 256]  -> 786432 floats
//   output/target features:    [4, 256, 64, 64]  -> B=4, C=256, N=4096
#define Bn   4
#define Cn   256
#define Nn   4096
#define IMG_ELEMS  786432
#define FEAT_ELEMS 4194304
#define EPS1 1e-8f
#define EPS2 1e-5f

// ---------------- device scratch (allocation-free: static globals) ----------
static __device__ __nv_bfloat16 g_Xh[Bn * Nn * Cn];   // centered out-feats bf16
static __device__ __nv_bfloat16 g_Yh[Bn * Nn * Cn];   // centered tgt-feats bf16
static __device__ float  g_mean[2][Bn * Cn];          // per-(b,c) means
static __device__ float  g_xn[Bn * Nn];               // row norms of X
static __device__ float  g_yn[Bn * Nn];               // row norms of Y
static __device__ __nv_bfloat16 g_cosh[(size_t)Bn * Nn * Nn]; // 128 MB cosine
static __device__ float  g_pS[Bn * Nn];               // per-row scale s = 1/(dmin+eps2)
static __device__ float  g_pA[Bn * Nn];               // per-row affine (1-s)-log(rowsum)
static __device__ float  g_cmax[32 * Bn * Nn];        // partial col maxima (32 x-chunks)
static __device__ float  g_cmax2[Bn * Nn];            // reduced col maxima
static __device__ double g_msep[2][512];              // MSE block partials

// ---------------- helpers ----------------------------------------------------
__device__ __forceinline__ uint32_t smem_u32(const void* p) {
    uint32_t a;
    asm("{ .reg .u64 t; cvta.to.shared.u64 t, %1; cvt.u32.u64 %0, t; }"
        : "=r"(a) : "l"(p));
    return a;
}
#define CP_ASYNC16(dst, src) \
    asm volatile("cp.async.cg.shared.global [%0], [%1], 16;" \
                 :: "r"(dst), "l"(src) : "memory")
#define CP_COMMIT() asm volatile("cp.async.commit_group;" ::: "memory")
#define CP_WAIT(n)  asm volatile("cp.async.wait_group %0;" :: "n"(n) : "memory")

__device__ __forceinline__ float2 bf2f(uint32_t u) {
    __nv_bfloat162 h;
    *reinterpret_cast<uint32_t*>(&h) = u;
    return __bfloat1622float2(h);
}

// ldmatrix x4: four 8x8 b16 tiles, addresses supplied per-lane
__device__ __forceinline__ void ldmx4(uint32_t* r, uint32_t addr) {
    asm volatile(
        "ldmatrix.sync.aligned.m8n8.x4.shared.b16 {%0,%1,%2,%3}, [%4];"
        : "=r"(r[0]), "=r"(r[1]), "=r"(r[2]), "=r"(r[3]) : "r"(addr));
}

// warp-level bf16 MMA: D(16x8,f32) += A(16x16) * B(16x8)
__device__ __forceinline__ void mma_bf16(float* d, const uint32_t* a,
                                         uint32_t b0, uint32_t b1) {
    asm volatile(
        "mma.sync.aligned.m16n8k16.row.col.f32.bf16.bf16.f32 "
        "{%0,%1,%2,%3}, {%4,%5,%6,%7}, {%8,%9}, {%0,%1,%2,%3};"
        : "+f"(d[0]), "+f"(d[1]), "+f"(d[2]), "+f"(d[3])
        : "r"(a[0]), "r"(a[1]), "r"(a[2]), "r"(a[3]), "r"(b0), "r"(b1));
}

// ---------------- 1. MSE partials (deterministic two-stage) ------------------
__global__ void __launch_bounds__(256) mse_kernel(const float* __restrict__ o,
                                                  const float* __restrict__ t,
                                                  const float* __restrict__ of,
                                                  const float* __restrict__ tf) {
    const int which = blockIdx.y;
    const float* a = which ? of : o;
    const float* c = which ? tf : t;
    const int n = which ? FEAT_ELEMS : IMG_ELEMS;
    double s = 0.0;
    for (int i = blockIdx.x * 256 + threadIdx.x; i < n; i += 512 * 256) {
        float d = a[i] - c[i];
        s += (double)d * (double)d;
    }
    __shared__ double sh[256];
    sh[threadIdx.x] = s;
    __syncthreads();
    for (int st = 128; st > 0; st >>= 1) {
        if (threadIdx.x < st) sh[threadIdx.x] += sh[threadIdx.x + st];
        __syncthreads();
    }
    if (threadIdx.x == 0) g_msep[which][blockIdx.x] = sh[0];
}

// ---------------- 2. per-(b,c) means over N positions ------------------------
__global__ void __launch_bounds__(256) mean_kernel(const float* __restrict__ of,
                                                   const float* __restrict__ tf) {
    const float* src = blockIdx.y ? tf : of;
    const int bc = blockIdx.x;
    const float* p = src + (size_t)bc * Nn;
    float s = 0.f;
    for (int i = threadIdx.x; i < Nn; i += 256) s += p[i];
    __shared__ float sh[256];
    sh[threadIdx.x] = s;
    __syncthreads();
    for (int st = 128; st > 0; st >>= 1) {
        if (threadIdx.x < st) sh[threadIdx.x] += sh[threadIdx.x + st];
        __syncthreads();
    }
    if (threadIdx.x == 0) g_mean[blockIdx.y][bc] = sh[0] * (1.f / Nn);
}

// ---------------- 3. transpose [C][N] -> [N][C], center, cast bf16 -----------
__global__ void __launch_bounds__(256) transpose_kernel(const float* __restrict__ of,
                                                        const float* __restrict__ tf) {
    const int tz = blockIdx.z;
    const int tensor = tz >> 2;
    const int b = tz & 3;
    const float* src = (tensor ? tf : of) + (size_t)b * Cn * Nn;
    __nv_bfloat16* dst = (tensor ? g_Yh : g_Xh) + (size_t)b * Nn * Cn;
    const float* mean = g_mean[tensor] + b * Cn;
    __shared__ float tile[32][33];
    const int tx = threadIdx.x, ty = threadIdx.y;  // 32 x 8
    const int n0 = blockIdx.x * 32, c0 = blockIdx.y * 32;
#pragma unroll
    for (int j = 0; j < 4; j++) {
        int c = c0 + ty + j * 8;
        tile[ty + j * 8][tx] = src[(size_t)c * Nn + n0 + tx] - mean[c];
    }
    __syncthreads();
#pragma unroll
    for (int j = 0; j < 4; j++) {
        int n = n0 + ty + j * 8;
        dst[(size_t)n * Cn + c0 + tx] = __float2bfloat16(tile[tx][ty + j * 8]);
    }
}

// ---------------- 4. per-row L2 norms (from bf16 rows) ------------------------
__global__ void __launch_bounds__(256) norm_kernel() {
    const int tensor = blockIdx.y;
    const __nv_bfloat16* X = tensor ? g_Yh : g_Xh;
    float* out = tensor ? g_yn : g_xn;
    const int warp = threadIdx.x >> 5, lane = threadIdx.x & 31;
    const int r = blockIdx.x * 8 + warp;
    const uint4* p = (const uint4*)(X + (size_t)r * Cn);
    uint4 q = p[lane];  // 8 bf16
    const uint32_t* w = (const uint32_t*)&q;
    float s = 0.f;
#pragma unroll
    for (int i = 0; i < 4; i++) {
        float2 f = bf2f(w[i]);
        s += f.x * f.x + f.y * f.y;
    }
    for (int o = 16; o; o >>= 1) s += __shfl_xor_sync(0xffffffffu, s, o);
    if (lane == 0) out[r] = sqrtf(s);
}

// ---------------- 5. bf16 mma.sync GEMM -> bf16 cosine matrix ----------------
// BM=128, BN=128, BK=32, 256 threads (8 warps, 2x4 grid, warp tile 64x32).
// 3-stage cp.async pipeline; ldmatrix.x4 fragments.
// Smem rows = 64 B; XOR swizzle on 16B groups: grp ^= (row>>1)&3.
__global__ void __launch_bounds__(256) gemm_mma_kernel() {
    __shared__ __align__(16) uint32_t smem[12288];  // 3 stages x (A 8KB | B 8KB)

    const int b = blockIdx.z;
    const int rowBase = blockIdx.y * 128, colBase = blockIdx.x * 128;
    const __nv_bfloat16* __restrict__ Xb = g_Xh + (size_t)b * (Nn * Cn);
    const __nv_bfloat16* __restrict__ Yb = g_Yh + (size_t)b * (Nn * Cn);
    const int tid = threadIdx.x;
    const int wid = tid >> 5, lane = tid & 31;
    const int wm = wid & 1, wn = wid >> 1;   // 2 along M, 4 along N
    const int g = lane >> 2, c = lane & 3;

    // cp.async staging: 128 rows x 64 B per operand per chunk; 2 xfers/thread/op
    const int row0 = tid >> 2, tq = tid & 3;
    const __nv_bfloat16* Agp = Xb + (size_t)(rowBase + row0) * Cn + tq * 8;
    const __nv_bfloat16* Bgp = Yb + (size_t)(colBase + row0) * Cn + tq * 8;
    const uint32_t sbase = smem_u32(smem);
    const uint32_t soff = (uint32_t)(row0 * 64 + (tq ^ ((row0 >> 1) & 3)) * 16);

#define ISSUE(ch, st) do {                                                    \
        const uint32_t dA = sbase + (uint32_t)(st) * 16384u + soff;           \
        const uint32_t dB = dA + 8192u;                                       \
        CP_ASYNC16(dA,        Agp + (ch) * 32);                               \
        CP_ASYNC16(dA + 4096, Agp + 64 * Cn + (ch) * 32);                     \
        CP_ASYNC16(dB,        Bgp + (ch) * 32);                               \
        CP_ASYNC16(dB + 4096, Bgp + 64 * Cn + (ch) * 32);                     \
        CP_COMMIT();                                                          \
    } while (0)

    float d[4][4][4];
#pragma unroll
    for (int mt = 0; mt < 4; mt++)
#pragma unroll
        for (int nt = 0; nt < 4; nt++)
#pragma unroll
            for (int k = 0; k < 4; k++) d[mt][nt][k] = 0.f;

    // ldmatrix per-lane address geometry
    const int arow = wm * 64 + (lane & 15);        // + mt*16
    const int ahi = lane >> 4;                     // k-halfgroup select
    const uint32_t asw = (uint32_t)((arow >> 1) & 3);
    const uint32_t aoff = (uint32_t)(arow * 64);
    const int brow = wn * 32 + lane;               // covers 4 n-tiles of 8 rows
    const uint32_t bsw = (uint32_t)((brow >> 1) & 3);
    const uint32_t boff = 8192u + (uint32_t)(brow * 64);

    ISSUE(0, 0);
    ISSUE(1, 1);
    int stage = 0;
    for (int ch = 0; ch < 8; ch++) {
        if (ch < 6) {
            int nst = stage + 2; if (nst >= 3) nst -= 3;
            ISSUE(ch + 2, nst);
            CP_WAIT(2);
        } else if (ch == 6) {
            CP_WAIT(1);
        } else {
            CP_WAIT(0);
        }
        __syncthreads();

        const uint32_t sb = sbase + (uint32_t)stage * 16384u;
        const uint32_t abase = sb + aoff;
        const uint32_t bbase = sb + boff;
#pragma unroll
        for (int kk = 0; kk < 2; kk++) {
            uint32_t af[4][4], b0[4], b1[4];
            const uint32_t akg = (uint32_t)(kk * 2 + ahi);
#pragma unroll
            for (int mt = 0; mt < 4; mt++)
                ldmx4(af[mt], abase + (uint32_t)(mt * 1024) + ((akg ^ asw) << 4));
            ldmx4(b0, bbase + (((uint32_t)(kk * 2) ^ bsw) << 4));
            ldmx4(b1, bbase + (((uint32_t)(kk * 2 + 1) ^ bsw) << 4));
#pragma unroll
            for (int mt = 0; mt < 4; mt++)
#pragma unroll
                for (int nt = 0; nt < 4; nt++)
                    mma_bf16(d[mt][nt], af[mt], b0[nt], b1[nt]);
        }
        __syncthreads();
        if (++stage == 3) stage = 0;
    }
#undef ISSUE

    // ---- epilogue: cosine normalization + bf16 store ----
    const float* xn = g_xn + (b << 12);
    const float* yn = g_yn + (b << 12);
    float xv[4][2], yv[4][2];
#pragma unroll
    for (int mt = 0; mt < 4; mt++) {
        const int r = rowBase + wm * 64 + mt * 16 + g;
        xv[mt][0] = xn[r];
        xv[mt][1] = xn[r + 8];
    }
#pragma unroll
    for (int nt = 0; nt < 4; nt++) {
        const int cc = colBase + wn * 32 + nt * 8 + 2 * c;
        yv[nt][0] = yn[cc];
        yv[nt][1] = yn[cc + 1];
    }
    __nv_bfloat16* Cb = g_cosh + ((size_t)b << 24);
#pragma unroll
    for (int mt = 0; mt < 4; mt++) {
        const int r = rowBase + wm * 64 + mt * 16 + g;
#pragma unroll
        for (int nt = 0; nt < 4; nt++) {
            const int cc = colBase + wn * 32 + nt * 8 + 2 * c;
            __nv_bfloat162 o0 = __floats2bfloat162_rn(
                d[mt][nt][0] / (xv[mt][0] * yv[nt][0] + EPS1),
                d[mt][nt][1] / (xv[mt][0] * yv[nt][1] + EPS1));
            __nv_bfloat162 o1 = __floats2bfloat162_rn(
                d[mt][nt][2] / (xv[mt][1] * yv[nt][0] + EPS1),
                d[mt][nt][3] / (xv[mt][1] * yv[nt][1] + EPS1));
            *(__nv_bfloat162*)(Cb + (size_t)r * Nn + cc) = o0;
            *(__nv_bfloat162*)(Cb + (size_t)(r + 8) * Nn + cc) = o1;
        }
    }
}

// ---------------- 6. row pass: warp-per-row, shfl-only reductions -------------
// d = 1-cos; s = 1/(dmin+eps2); w_y = exp((1-s) + cos_y*s)
__global__ void __launch_bounds__(256) rowpass_kernel() {
    const int warp = threadIdx.x >> 5, lane = threadIdx.x & 31;
    const int r = blockIdx.x * 8 + warp;  // b*Nn + x
    const uint4* row = (const uint4*)(g_cosh + (size_t)r * Nn);
    uint4 q[16];
#pragma unroll
    for (int j = 0; j < 16; j++) q[j] = row[lane + 32 * j];

    float m = -1e30f;
#pragma unroll
    for (int j = 0; j < 16; j++) {
        const uint32_t* w = (const uint32_t*)&q[j];
#pragma unroll
        for (int i = 0; i < 4; i++) {
            float2 f = bf2f(w[i]);
            m = fmaxf(m, fmaxf(f.x, f.y));
        }
    }
    for (int o = 16; o; o >>= 1) m = fmaxf(m, __shfl_xor_sync(0xffffffffu, m, o));

    const float s = 1.f / (1.f - m + EPS2);
    const float a = 1.f - s;
    float sum = 0.f;
#pragma unroll
    for (int j = 0; j < 16; j++) {
        const uint32_t* w = (const uint32_t*)&q[j];
#pragma unroll
        for (int i = 0; i < 4; i++) {
            float2 f = bf2f(w[i]);
            sum += __expf(fmaf(f.x, s, a)) + __expf(fmaf(f.y, s, a));
        }
    }
    for (int o = 16; o; o >>= 1) sum += __shfl_xor_sync(0xffffffffu, sum, o);

    if (lane == 0) {
        g_pS[r] = s;
        g_pA[r] = a - logf(sum);
    }
}

// ---------------- 7. column pass: partial max over x (log-domain) ------------
// 32 x-chunks of 128 rows; 4 y per thread via uint2 loads; 512 blocks.
__global__ void __launch_bounds__(256) colpass_kernel() {
    const int tid = threadIdx.x;
    const int y = blockIdx.x * 1024 + tid * 4;  // grid.x = 4
    const int chunk = blockIdx.y;               // 0..31 (128 x-rows each)
    const int b = blockIdx.z;                   // 0..3
    __shared__ float ss[128], sa[128];
    const int r0 = (b << 12) + (chunk << 7);
    if (tid < 128) {
        ss[tid] = g_pS[r0 + tid];
        sa[tid] = g_pA[r0 + tid];
    }
    __syncthreads();
    const uint2* base = (const uint2*)(g_cosh + ((size_t)b << 24) +
                                       ((size_t)chunk << 19)) + (y >> 2);
    float m0 = -1e30f, m1 = -1e30f, m2 = -1e30f, m3 = -1e30f;
#pragma unroll 8
    for (int x = 0; x < 128; x++) {
        uint2 u = base[(size_t)x << 10];
        const float sx = ss[x], ax = sa[x];
        float2 f0 = bf2f(u.x);
        float2 f1 = bf2f(u.y);
        m0 = fmaxf(m0, fmaf(f0.x, sx, ax));
        m1 = fmaxf(m1, fmaf(f0.y, sx, ax));
        m2 = fmaxf(m2, fmaf(f1.x, sx, ax));
        m3 = fmaxf(m3, fmaf(f1.y, sx, ax));
    }
    float* out = g_cmax + (chunk << 14) + (b << 12) + y;
    out[0] = m0; out[1] = m1; out[2] = m2; out[3] = m3;
}

// ---------------- 7b. reduce 32 chunk partials -> g_cmax2 --------------------
__global__ void __launch_bounds__(256) colreduce_kernel() {
    const int i = blockIdx.x * 256 + threadIdx.x;  // 0..16383
    float m = -1e30f;
#pragma unroll
    for (int ch = 0; ch < 32; ch++) m = fmaxf(m, g_cmax[(ch << 14) + i]);
    g_cmax2[i] = m;
}

// ---------------- 8. final: CS, MSEs, loss -----------------------------------
__global__ void __launch_bounds__(256) final_kernel(float* __restrict__ out) {
    const int tid = threadIdx.x;
    double cs = 0.0;
    for (int i = tid; i < Bn * Nn; i += 256) cs += exp((double)g_cmax2[i]);
    double m1 = 0.0, m2 = 0.0;
    for (int i = tid; i < 512; i += 256) {
        m1 += g_msep[0][i];
        m2 += g_msep[1][i];
    }
    __shared__ double sh[3][256];
    sh[0][tid] = cs; sh[1][tid] = m1; sh[2][tid] = m2;
    __syncthreads();
    for (int st = 128; st > 0; st >>= 1) {
        if (tid < st) {
            sh[0][tid] += sh[0][tid + st];
            sh[1][tid] += sh[1][tid + st];
            sh[2][tid] += sh[2][tid + st];
        }
        __syncthreads();
    }
    if (tid == 0) {
        double CS = sh[0][0] / (double)(Bn * Nn);
        double mse1 = sh[1][0] / (double)IMG_ELEMS;
        double perc = sh[2][0] / (double)FEAT_ELEMS;
        out[0] = (float)(mse1 - log(CS) + 0.02 * perc);
    }
}

// ---------------- launch ------------------------------------------------------
extern "C" void kernel_launch(void* const* d_in, const int* in_sizes, int n_in,
                              void* d_out, int out_size) {
    const float* outputs = (const float*)d_in[0];
    const float* targets = (const float*)d_in[1];
    const float* of = (const float*)d_in[2];
    const float* tf = (const float*)d_in[3];
    float* out = (float*)d_out;

    mse_kernel<<<dim3(512, 2), 256>>>(outputs, targets, of, tf);
    mean_kernel<<<dim3(Bn * Cn, 2), 256>>>(of, tf);
    transpose_kernel<<<dim3(Nn / 32, Cn / 32, 2 * Bn), dim3(32, 8)>>>(of, tf);
    norm_kernel<<<dim3(Bn * Nn / 8, 2), 256>>>();
    gemm_mma_kernel<<<dim3(Nn / 128, Nn / 128, Bn), 256>>>();
    rowpass_kernel<<<Bn * Nn / 8, 256>>>();
    colpass_kernel<<<dim3(4, 32, Bn), 256>>>();
    colreduce_kernel<<<Bn * Nn / 256, 256>>>();
    final_kernel<<<1, 256>>>(out);
}